// round 1
// baseline (speedup 1.0000x reference)
#include <cuda_runtime.h>
#include <math.h>

#define WTOT 4096
#define CHUNK 64
#define HDIM 128
#define BATCH 64
#define NCHUNK (WTOT / CHUNK)

// Scratch: partial weighted sums and partial exp-sums per (b, chunk)
__device__ float g_pvec[BATCH * NCHUNK * HDIM]; // 2 MB
__device__ float g_psum[BATCH * NCHUNK];

__device__ __forceinline__ float warp_sum(float p) {
    #pragma unroll
    for (int o = 16; o > 0; o >>= 1) p += __shfl_down_sync(0xffffffffu, p, o);
    return p;
}

__device__ __forceinline__ float sigmoidf_(float x) {
    return 1.0f / (1.0f + expf(-x));
}

// ---------------------------------------------------------------------------
// Kernel A: fused score + exp + partial weighted-sum over encoder_output.
// One pass over the 128 MB tensor. grid = (NCHUNK, BATCH), 256 threads.
// weight logit of global row w is: 0 if w==0 else score(w-1),
// where score(w) = dot(enc[b,w,:], wa_enc) + dot(h0[1,b]*c0[1,b], wa_st) + att_b.
// ---------------------------------------------------------------------------
__global__ void __launch_bounds__(256) attn_kernel(
    const float* __restrict__ enc,
    const float* __restrict__ h0,
    const float* __restrict__ c0,
    const float* __restrict__ attW,   // [2*H]: [:H]=wa_enc, [H:]=wa_st
    const float* __restrict__ attb)   // [1]
{
    __shared__ float tile[CHUNK * HDIM];   // 32 KB
    __shared__ float wa_sh[HDIM];
    __shared__ float s_sh[CHUNK];
    __shared__ float e_sh[CHUNK];
    __shared__ float red[4];
    __shared__ float bias_sh;
    __shared__ float sprev_sh;
    __shared__ float vec_sh[HDIM];

    const int chunk = blockIdx.x;
    const int b     = blockIdx.y;
    const int tid   = threadIdx.x;
    const int lane  = tid & 31;
    const int wrp   = tid >> 5;
    const int start = chunk * CHUNK;

    const float* encb = enc + ((size_t)b * WTOT + start) * HDIM;

    // Stage wa_enc + compute attention-state bias (layer-1 h*c dot wa_st)
    if (tid < HDIM) {
        wa_sh[tid] = attW[tid];
        float p = h0[BATCH * HDIM + b * HDIM + tid]
                * c0[BATCH * HDIM + b * HDIM + tid]
                * attW[HDIM + tid];
        p = warp_sum(p);
        if (lane == 0) red[wrp] = p;
    }

    // Stage the 64x128 tile (2048 float4, 8 per thread, coalesced)
    {
        const float4* src = (const float4*)encb;
        float4*       dst = (float4*)tile;
        #pragma unroll
        for (int i = 0; i < 8; i++) dst[tid + 256 * i] = src[tid + 256 * i];
    }
    __syncthreads();
    if (tid == 0) bias_sh = red[0] + red[1] + red[2] + red[3] + attb[0];
    __syncthreads();
    const float bias = bias_sh;

    // Phase 1: per-row scores. 8 warps x 8 rows, warp-dot over 128.
    const float4 wv = ((const float4*)wa_sh)[lane];
    #pragma unroll
    for (int r = 0; r < 8; r++) {
        const int j = wrp * 8 + r;
        const float4 a = ((const float4*)tile)[j * 32 + lane];
        float p = a.x * wv.x + a.y * wv.y + a.z * wv.z + a.w * wv.w;
        p = warp_sum(p);
        if (lane == 0) s_sh[j] = p + bias;
    }
    // Score of row (start-1) from the previous chunk (1 extra row read).
    if (wrp == 0 && start > 0) {
        const float4* pr = (const float4*)(enc + ((size_t)b * WTOT + start - 1) * HDIM);
        const float4 a = pr[lane];
        float p = a.x * wv.x + a.y * wv.y + a.z * wv.z + a.w * wv.w;
        p = warp_sum(p);
        if (lane == 0) sprev_sh = p + bias;
    }
    __syncthreads();

    if (tid < CHUNK) {
        float logit;
        if (tid == 0) logit = (start == 0) ? 0.0f : sprev_sh;
        else          logit = s_sh[tid - 1];
        e_sh[tid] = expf(logit);
    }
    __syncthreads();

    // Phase 2: partial weighted sum. 2 row-groups x 128 h-threads.
    {
        const int h   = tid & 127;
        const int grp = tid >> 7;   // 0 or 1
        float acc = 0.0f;
        #pragma unroll
        for (int r = 0; r < 32; r++) {
            const int j = grp * 32 + r;
            acc += e_sh[j] * tile[j * HDIM + h];
        }
        if (grp == 0) vec_sh[h] = acc;
        __syncthreads();
        if (grp == 1) vec_sh[h] += acc;   // single writer per h
        __syncthreads();
        if (tid < HDIM)
            g_pvec[((size_t)b * NCHUNK + chunk) * HDIM + tid] = vec_sh[tid];
    }
    if (wrp == 0) {
        float s = e_sh[lane] + e_sh[lane + 32];
        s = warp_sum(s);
        if (lane == 0) g_psum[b * NCHUNK + chunk] = s;
    }
}

// ---------------------------------------------------------------------------
// Kernel B: reduce partials -> context x; xin GEMV; LSTM layer 0; LSTM layer 1.
// grid = 64 (one block per batch), 256 threads.
// Output layout: [h2 as (B,1,H) | h_stack (2,B,H) | c_stack (2,B,H)]
// ---------------------------------------------------------------------------
__device__ __forceinline__ void lstm_layer(
    const float* __restrict__ x_sh,     // [128] smem
    const float* __restrict__ hp_sh,    // [128] smem (staged h_prev)
    const float* __restrict__ cprev_g,  // [128] gmem
    const float* __restrict__ Wih, const float* __restrict__ Whh,
    const float* __restrict__ bih, const float* __restrict__ bhh,
    float* gate_sh, float* hnew_sh,
    float* __restrict__ c_out_g, float* __restrict__ h_out_g,
    float* __restrict__ extra_h_out,    // may be nullptr
    int tid)
{
    const int lane = tid & 31, wrp = tid >> 5;
    const float4 xv = ((const float4*)x_sh)[lane];
    const float4 hv = ((const float4*)hp_sh)[lane];
    // 8 warps x 64 gates each; each gate = 256-wide dot via warp reduce
    for (int t = 0; t < 64; t++) {
        const int k = wrp * 64 + t;
        const float4 wi = ((const float4*)(Wih + k * HDIM))[lane];
        const float4 wh = ((const float4*)(Whh + k * HDIM))[lane];
        float p = wi.x * xv.x + wi.y * xv.y + wi.z * xv.z + wi.w * xv.w
                + wh.x * hv.x + wh.y * hv.y + wh.z * hv.z + wh.w * hv.w;
        p = warp_sum(p);
        if (lane == 0) gate_sh[k] = p + bih[k] + bhh[k];
    }
    __syncthreads();
    if (tid < HDIM) {
        const float ig = gate_sh[tid];
        const float fg = gate_sh[128 + tid];
        const float gg = gate_sh[256 + tid];
        const float og = gate_sh[384 + tid];
        const float cprev = cprev_g[tid];
        const float cn = sigmoidf_(fg) * cprev + sigmoidf_(ig) * tanhf(gg);
        const float hn = sigmoidf_(og) * tanhf(cn);
        hnew_sh[tid] = hn;
        c_out_g[tid] = cn;
        h_out_g[tid] = hn;
        if (extra_h_out) extra_h_out[tid] = hn;
    }
    __syncthreads();
}

__global__ void __launch_bounds__(256) decode_kernel(
    const float* __restrict__ input,
    const float* __restrict__ h0,
    const float* __restrict__ c0,
    const float* __restrict__ inp_W, const float* __restrict__ inp_b,
    const float* __restrict__ W_ih0, const float* __restrict__ W_hh0,
    const float* __restrict__ b_ih0, const float* __restrict__ b_hh0,
    const float* __restrict__ W_ih1, const float* __restrict__ W_hh1,
    const float* __restrict__ b_ih1, const float* __restrict__ b_hh1,
    float* __restrict__ out)
{
    __shared__ float cat_sh[256];
    __shared__ float xin_sh[HDIM];
    __shared__ float gate_sh[512];
    __shared__ float hp_sh[HDIM];
    __shared__ float h1_sh[HDIM];
    __shared__ float h2_sh[HDIM];
    __shared__ float sarr[NCHUNK];
    __shared__ float S_sh;

    const int b = blockIdx.x;
    const int tid = threadIdx.x, lane = tid & 31, wrp = tid >> 5;

    // Reduce exp-sum and weighted-vec partials
    if (tid < NCHUNK) sarr[tid] = g_psum[b * NCHUNK + tid];
    float vacc = 0.0f;
    if (tid < HDIM) {
        #pragma unroll 8
        for (int c = 0; c < NCHUNK; c++)
            vacc += g_pvec[((size_t)b * NCHUNK + c) * HDIM + tid];
    }
    __syncthreads();
    if (wrp == 0) {
        float s = sarr[lane] + sarr[lane + 32];
        s = warp_sum(s);
        if (lane == 0) S_sh = s;
    }
    __syncthreads();
    if (tid < HDIM) {
        cat_sh[tid]       = vacc / S_sh;           // context x
        cat_sh[HDIM + tid] = input[b * HDIM + tid]; // decoder input
    }
    __syncthreads();

    // xin = cat @ inp_W.T + inp_b   (8 warps x 16 outputs, K=256)
    for (int t = 0; t < 16; t++) {
        const int i = wrp * 16 + t;
        const float4* wrow = (const float4*)(inp_W + i * 256);
        const float4 a0 = wrow[lane];
        const float4 a1 = wrow[lane + 32];
        const float4 c0v = ((const float4*)cat_sh)[lane];
        const float4 c1v = ((const float4*)cat_sh)[lane + 32];
        float p = a0.x * c0v.x + a0.y * c0v.y + a0.z * c0v.z + a0.w * c0v.w
                + a1.x * c1v.x + a1.y * c1v.y + a1.z * c1v.z + a1.w * c1v.w;
        p = warp_sum(p);
        if (lane == 0) xin_sh[i] = p + inp_b[i];
    }
    __syncthreads();

    // Output layout offsets
    float* out_h1 = out + 8192 + b * HDIM;                 // h_stack[0]
    float* out_h2 = out + 8192 + 8192 + b * HDIM;          // h_stack[1]
    float* out_c1 = out + 24576 + b * HDIM;                // c_stack[0]
    float* out_c2 = out + 24576 + 8192 + b * HDIM;         // c_stack[1]
    float* out_y  = out + b * HDIM;                        // output (B,1,H)

    // LSTM layer 0
    if (tid < HDIM) hp_sh[tid] = h0[b * HDIM + tid];
    __syncthreads();
    lstm_layer(xin_sh, hp_sh, c0 + b * HDIM,
               W_ih0, W_hh0, b_ih0, b_hh0,
               gate_sh, h1_sh, out_c1, out_h1, nullptr, tid);

    // LSTM layer 1
    if (tid < HDIM) hp_sh[tid] = h0[BATCH * HDIM + b * HDIM + tid];
    __syncthreads();
    lstm_layer(h1_sh, hp_sh, c0 + BATCH * HDIM + b * HDIM,
               W_ih1, W_hh1, b_ih1, b_hh1,
               gate_sh, h2_sh, out_c2, out_h2, out_y, tid);
}

extern "C" void kernel_launch(void* const* d_in, const int* in_sizes, int n_in,
                              void* d_out, int out_size)
{
    const float* input  = (const float*)d_in[0];
    const float* h0     = (const float*)d_in[1];
    const float* c0     = (const float*)d_in[2];
    const float* enc    = (const float*)d_in[3];
    const float* attW   = (const float*)d_in[4];
    const float* attb   = (const float*)d_in[5];
    const float* inp_W  = (const float*)d_in[6];
    const float* inp_b  = (const float*)d_in[7];
    const float* W_ih0  = (const float*)d_in[8];
    const float* W_hh0  = (const float*)d_in[9];
    const float* b_ih0  = (const float*)d_in[10];
    const float* b_hh0  = (const float*)d_in[11];
    const float* W_ih1  = (const float*)d_in[12];
    const float* W_hh1  = (const float*)d_in[13];
    const float* b_ih1  = (const float*)d_in[14];
    const float* b_hh1  = (const float*)d_in[15];
    float* out = (float*)d_out;

    attn_kernel<<<dim3(NCHUNK, BATCH), 256>>>(enc, h0, c0, attW, attb);
    decode_kernel<<<BATCH, 256>>>(input, h0, c0, inp_W, inp_b,
                                  W_ih0, W_hh0, b_ih0, b_hh0,
                                  W_ih1, W_hh1, b_ih1, b_hh1, out);
}

// round 2
// speedup vs baseline: 1.8273x; 1.8273x over previous
#include <cuda_runtime.h>
#include <math.h>

#define WTOT 4096
#define CHUNK 64
#define HDIM 128
#define BATCH 64
#define NCHUNK (WTOT / CHUNK)

__device__ float g_pvec[BATCH * NCHUNK * HDIM]; // 2 MB partial weighted sums
__device__ float g_psum[BATCH * NCHUNK];        // partial exp sums

__device__ __forceinline__ float warp_sum(float p) {
    #pragma unroll
    for (int o = 16; o > 0; o >>= 1) p += __shfl_down_sync(0xffffffffu, p, o);
    return p;
}

__device__ __forceinline__ float sigmoidf_(float x) {
    return 1.0f / (1.0f + expf(-x));
}

// ---------------------------------------------------------------------------
// Kernel A: fused stage + score + exp + partial weighted-sum.
// Score dot is computed DURING the global->smem staging (thread t's float4s
// all belong to row (wrp + 8i), column-part lane), so one smem pass + one
// barrier are eliminated vs R1.
// ---------------------------------------------------------------------------
__global__ void __launch_bounds__(256) attn_kernel(
    const float* __restrict__ enc,
    const float* __restrict__ h0,
    const float* __restrict__ c0,
    const float* __restrict__ attW,
    const float* __restrict__ attb)
{
    __shared__ float tile[CHUNK * HDIM];   // 32 KB
    __shared__ float wa_sh[HDIM];
    __shared__ float s_sh[CHUNK];
    __shared__ float e_sh[CHUNK];
    __shared__ float red[4];
    __shared__ float bias_sh;
    __shared__ float sprev_sh;
    __shared__ float vec_sh[HDIM];

    const int chunk = blockIdx.x;
    const int b     = blockIdx.y;
    const int tid   = threadIdx.x;
    const int lane  = tid & 31;
    const int wrp   = tid >> 5;
    const int start = chunk * CHUNK;

    const float* encb = enc + ((size_t)b * WTOT + start) * HDIM;

    // Stage wa_enc + attention-state bias
    if (tid < HDIM) {
        wa_sh[tid] = attW[tid];
        float p = h0[BATCH * HDIM + b * HDIM + tid]
                * c0[BATCH * HDIM + b * HDIM + tid]
                * attW[HDIM + tid];
        p = warp_sum(p);
        if (lane == 0) red[wrp] = p;
    }
    __syncthreads();
    if (tid == 0) bias_sh = red[0] + red[1] + red[2] + red[3] + attb[0];

    // Fused stage+score: thread t's float4 index f = t + 256*i
    // -> row = f>>5 = wrp + 8*i, col-part = f&31 = lane.
    const float4 wv = ((const float4*)wa_sh)[lane];
    float pr[8];
    {
        const float4* src = (const float4*)encb;
        float4*       dst = (float4*)tile;
        #pragma unroll
        for (int i = 0; i < 8; i++) {
            const float4 v = src[tid + 256 * i];
            dst[tid + 256 * i] = v;
            pr[i] = v.x * wv.x + v.y * wv.y + v.z * wv.z + v.w * wv.w;
        }
    }
    // Extra row (start-1) score for the shifted softmax alignment.
    float pprev = 0.0f;
    if (wrp == 0 && start > 0) {
        const float4 a = ((const float4*)(enc + ((size_t)b * WTOT + start - 1) * HDIM))[lane];
        pprev = a.x * wv.x + a.y * wv.y + a.z * wv.z + a.w * wv.w;
    }
    __syncthreads();                    // bias_sh ready
    const float bias = bias_sh;
    #pragma unroll
    for (int i = 0; i < 8; i++) {
        float s = warp_sum(pr[i]);
        if (lane == 0) s_sh[wrp + 8 * i] = s + bias;
    }
    if (wrp == 0 && start > 0) {
        float s = warp_sum(pprev);
        if (lane == 0) sprev_sh = s + bias;
    }
    __syncthreads();

    if (tid < CHUNK) {
        float logit;
        if (tid == 0) logit = (start == 0) ? 0.0f : sprev_sh;
        else          logit = s_sh[tid - 1];
        e_sh[tid] = expf(logit);
    }
    __syncthreads();

    // Partial weighted sum: 2 row-groups x 128 h-threads.
    {
        const int h   = tid & 127;
        const int grp = tid >> 7;
        float acc = 0.0f;
        #pragma unroll
        for (int r = 0; r < 32; r++) {
            const int j = grp * 32 + r;
            acc += e_sh[j] * tile[j * HDIM + h];
        }
        if (grp == 0) vec_sh[h] = acc;
        __syncthreads();
        if (grp == 1) vec_sh[h] += acc;
        __syncthreads();
        if (tid < HDIM)
            g_pvec[((size_t)b * NCHUNK + chunk) * HDIM + tid] = vec_sh[tid];
    }
    if (wrp == 0) {
        float s = e_sh[lane] + e_sh[lane + 32];
        s = warp_sum(s);
        if (lane == 0) g_psum[b * NCHUNK + chunk] = s;
    }
}

// ---------------------------------------------------------------------------
// Kernel B: 1024 threads/block (32 warps) -> only 16 serial warp-dots per
// LSTM layer instead of 64.
// ---------------------------------------------------------------------------
__device__ __forceinline__ void lstm_layer(
    const float* __restrict__ x_sh,
    const float* __restrict__ hp_sh,
    const float* __restrict__ cprev_g,
    const float* __restrict__ Wih, const float* __restrict__ Whh,
    const float* __restrict__ bih, const float* __restrict__ bhh,
    float* gate_sh, float* hnew_sh,
    float* __restrict__ c_out_g, float* __restrict__ h_out_g,
    float* __restrict__ extra_h_out,
    int tid)
{
    const int lane = tid & 31, wrp = tid >> 5;
    const float4 xv = ((const float4*)x_sh)[lane];
    const float4 hv = ((const float4*)hp_sh)[lane];
    // 32 warps x 16 gates each, K=256 warp-dot
    #pragma unroll 4
    for (int t = 0; t < 16; t++) {
        const int k = wrp * 16 + t;
        const float4 wi = ((const float4*)(Wih + k * HDIM))[lane];
        const float4 wh = ((const float4*)(Whh + k * HDIM))[lane];
        float p = wi.x * xv.x + wi.y * xv.y + wi.z * xv.z + wi.w * xv.w
                + wh.x * hv.x + wh.y * hv.y + wh.z * hv.z + wh.w * hv.w;
        p = warp_sum(p);
        if (lane == 0) gate_sh[k] = p + bih[k] + bhh[k];
    }
    __syncthreads();
    if (tid < HDIM) {
        const float ig = gate_sh[tid];
        const float fg = gate_sh[128 + tid];
        const float gg = gate_sh[256 + tid];
        const float og = gate_sh[384 + tid];
        const float cn = sigmoidf_(fg) * cprev_g[tid] + sigmoidf_(ig) * tanhf(gg);
        const float hn = sigmoidf_(og) * tanhf(cn);
        hnew_sh[tid] = hn;
        c_out_g[tid] = cn;
        h_out_g[tid] = hn;
        if (extra_h_out) extra_h_out[tid] = hn;
    }
    __syncthreads();
}

__global__ void __launch_bounds__(1024) decode_kernel(
    const float* __restrict__ input,
    const float* __restrict__ h0,
    const float* __restrict__ c0,
    const float* __restrict__ inp_W, const float* __restrict__ inp_b,
    const float* __restrict__ W_ih0, const float* __restrict__ W_hh0,
    const float* __restrict__ b_ih0, const float* __restrict__ b_hh0,
    const float* __restrict__ W_ih1, const float* __restrict__ W_hh1,
    const float* __restrict__ b_ih1, const float* __restrict__ b_hh1,
    float* __restrict__ out)
{
    __shared__ float cat_sh[256];
    __shared__ float xin_sh[HDIM];
    __shared__ float gate_sh[512];
    __shared__ float hp_sh[HDIM];
    __shared__ float h1_sh[HDIM];
    __shared__ float h2_sh[HDIM];
    __shared__ float vred[8][HDIM];
    __shared__ float sarr[NCHUNK];
    __shared__ float S_sh;

    const int b = blockIdx.x;
    const int tid = threadIdx.x, lane = tid & 31, wrp = tid >> 5;

    // Stage 0: reduce partials (8 groups x 8 chunks each, deep MLP)
    if (tid < NCHUNK) sarr[tid] = g_psum[b * NCHUNK + tid];
    {
        const int h = tid & 127, grp = tid >> 7;
        float v = 0.0f;
        #pragma unroll
        for (int c = 0; c < 8; c++)
            v += g_pvec[((size_t)b * NCHUNK + grp * 8 + c) * HDIM + h];
        vred[grp][h] = v;
    }
    __syncthreads();
    float vcol = 0.0f;
    if (tid < HDIM) {
        #pragma unroll
        for (int g = 0; g < 8; g++) vcol += vred[g][tid];
    }
    if (wrp == 0) {
        float s = sarr[lane] + sarr[lane + 32];
        s = warp_sum(s);
        if (lane == 0) S_sh = s;
    }
    __syncthreads();
    if (tid < HDIM) {
        cat_sh[tid]        = vcol / S_sh;
        cat_sh[HDIM + tid] = input[b * HDIM + tid];
        hp_sh[tid]         = h0[b * HDIM + tid];
    }
    __syncthreads();

    // xin: 32 warps x 4 outputs, K=256
    #pragma unroll
    for (int t = 0; t < 4; t++) {
        const int i = wrp * 4 + t;
        const float4* wrow = (const float4*)(inp_W + i * 256);
        const float4 a0 = wrow[lane];
        const float4 a1 = wrow[lane + 32];
        const float4 c0v = ((const float4*)cat_sh)[lane];
        const float4 c1v = ((const float4*)cat_sh)[lane + 32];
        float p = a0.x * c0v.x + a0.y * c0v.y + a0.z * c0v.z + a0.w * c0v.w
                + a1.x * c1v.x + a1.y * c1v.y + a1.z * c1v.z + a1.w * c1v.w;
        p = warp_sum(p);
        if (lane == 0) xin_sh[i] = p + inp_b[i];
    }
    __syncthreads();

    float* out_h1 = out + 8192 + b * HDIM;
    float* out_h2 = out + 16384 + b * HDIM;
    float* out_c1 = out + 24576 + b * HDIM;
    float* out_c2 = out + 32768 + b * HDIM;
    float* out_y  = out + b * HDIM;

    lstm_layer(xin_sh, hp_sh, c0 + b * HDIM,
               W_ih0, W_hh0, b_ih0, b_hh0,
               gate_sh, h1_sh, out_c1, out_h1, nullptr, tid);

    if (tid < HDIM) hp_sh[tid] = h0[BATCH * HDIM + b * HDIM + tid];
    __syncthreads();
    lstm_layer(h1_sh, hp_sh, c0 + BATCH * HDIM + b * HDIM,
               W_ih1, W_hh1, b_ih1, b_hh1,
               gate_sh, h2_sh, out_c2, out_h2, out_y, tid);
}

extern "C" void kernel_launch(void* const* d_in, const int* in_sizes, int n_in,
                              void* d_out, int out_size)
{
    const float* input  = (const float*)d_in[0];
    const float* h0     = (const float*)d_in[1];
    const float* c0     = (const float*)d_in[2];
    const float* enc    = (const float*)d_in[3];
    const float* attW   = (const float*)d_in[4];
    const float* attb   = (const float*)d_in[5];
    const float* inp_W  = (const float*)d_in[6];
    const float* inp_b  = (const float*)d_in[7];
    const float* W_ih0  = (const float*)d_in[8];
    const float* W_hh0  = (const float*)d_in[9];
    const float* b_ih0  = (const float*)d_in[10];
    const float* b_hh0  = (const float*)d_in[11];
    const float* W_ih1  = (const float*)d_in[12];
    const float* W_hh1  = (const float*)d_in[13];
    const float* b_ih1  = (const float*)d_in[14];
    const float* b_hh1  = (const float*)d_in[15];
    float* out = (float*)d_out;

    attn_kernel<<<dim3(NCHUNK, BATCH), 256>>>(enc, h0, c0, attW, attb);
    decode_kernel<<<BATCH, 1024>>>(input, h0, c0, inp_W, inp_b,
                                   W_ih0, W_hh0, b_ih0, b_hh0,
                                   W_ih1, W_hh1, b_ih1, b_hh1, out);
}

// round 4
// speedup vs baseline: 2.0935x; 1.1456x over previous
#include <cuda_runtime.h>
#include <math.h>

#define WTOT 4096
#define CHUNK 64
#define HDIM 128
#define BATCH 64
#define NCHUNK (WTOT / CHUNK)
#define NPRE 512          // precompute blocks (b x 8 gate-groups)

__device__ float g_pvec[BATCH * NCHUNK * HDIM]; // partial weighted sums (2 MB)
__device__ float g_psum[BATCH * NCHUNK];        // partial exp sums
__device__ float g_pre0[BATCH * 512];           // W_hh0*h0[0] + b_ih0 + b_hh0
__device__ float g_pre1[BATCH * 512];           // W_hh1*h0[1] + b_ih1 + b_hh1

__device__ __forceinline__ float warp_sum(float p) {
    #pragma unroll
    for (int o = 16; o > 0; o >>= 1) p += __shfl_down_sync(0xffffffffu, p, o);
    return p;
}

__device__ __forceinline__ float sigmoidf_(float x) {
    return 1.0f / (1.0f + expf(-x));
}

// ---------------------------------------------------------------------------
// Kernel 1: unified grid. Blocks [0, NPRE) precompute hidden-weight gate
// halves (hidden under the attention sweep); blocks [NPRE, NPRE+4096) do the
// fused stage+score+exp+partial-weighted-sum attention pass.
// ---------------------------------------------------------------------------
__global__ void __launch_bounds__(256) attn_pre_kernel(
    const float* __restrict__ enc,
    const float* __restrict__ h0,
    const float* __restrict__ c0,
    const float* __restrict__ attW,
    const float* __restrict__ attb,
    const float* __restrict__ W_hh0,
    const float* __restrict__ b_ih0, const float* __restrict__ b_hh0,
    const float* __restrict__ W_hh1,
    const float* __restrict__ b_ih1, const float* __restrict__ b_hh1)
{
    const int tid  = threadIdx.x;
    const int lane = tid & 31;
    const int wrp  = tid >> 5;

    if (blockIdx.x < NPRE) {
        // ---- precompute block: b = idx>>3, gate group kg = idx&7 (64 gates)
        const int b  = blockIdx.x >> 3;
        const int k0 = (blockIdx.x & 7) * 64;
        const float4 hv0 = ((const float4*)(h0 + b * HDIM))[lane];
        const float4 hv1 = ((const float4*)(h0 + BATCH * HDIM + b * HDIM))[lane];
        // 8 warps x 8 gates per layer
        #pragma unroll 4
        for (int t = 0; t < 8; t++) {
            const int k = k0 + wrp * 8 + t;
            const float4 w0 = ((const float4*)(W_hh0 + k * HDIM))[lane];
            float p0 = w0.x * hv0.x + w0.y * hv0.y + w0.z * hv0.z + w0.w * hv0.w;
            p0 = warp_sum(p0);
            if (lane == 0) g_pre0[b * 512 + k] = p0 + b_ih0[k] + b_hh0[k];
        }
        #pragma unroll 4
        for (int t = 0; t < 8; t++) {
            const int k = k0 + wrp * 8 + t;
            const float4 w1 = ((const float4*)(W_hh1 + k * HDIM))[lane];
            float p1 = w1.x * hv1.x + w1.y * hv1.y + w1.z * hv1.z + w1.w * hv1.w;
            p1 = warp_sum(p1);
            if (lane == 0) g_pre1[b * 512 + k] = p1 + b_ih1[k] + b_hh1[k];
        }
        return;
    }

    // ---- attention block
    __shared__ float tile[CHUNK * HDIM];   // 32 KB
    __shared__ float wa_sh[HDIM];
    __shared__ float s_sh[CHUNK];
    __shared__ float e_sh[CHUNK];
    __shared__ float red[4];
    __shared__ float bias_sh;
    __shared__ float sprev_sh;
    __shared__ float vec_sh[HDIM];

    const int cid   = blockIdx.x - NPRE;
    const int chunk = cid & (NCHUNK - 1);
    const int b     = cid >> 6;
    const int start = chunk * CHUNK;

    const float* encb = enc + ((size_t)b * WTOT + start) * HDIM;

    if (tid < HDIM) {
        wa_sh[tid] = attW[tid];
        float p = h0[BATCH * HDIM + b * HDIM + tid]
                * c0[BATCH * HDIM + b * HDIM + tid]
                * attW[HDIM + tid];
        p = warp_sum(p);
        if (lane == 0) red[wrp] = p;
    }
    __syncthreads();
    if (tid == 0) bias_sh = red[0] + red[1] + red[2] + red[3] + attb[0];

    // Fused stage+score: float4 index f = tid + 256*i -> row wrp+8i, col lane
    const float4 wv = ((const float4*)wa_sh)[lane];
    float pr[8];
    {
        const float4* src = (const float4*)encb;
        float4*       dst = (float4*)tile;
        #pragma unroll
        for (int i = 0; i < 8; i++) {
            const float4 v = src[tid + 256 * i];
            dst[tid + 256 * i] = v;
            pr[i] = v.x * wv.x + v.y * wv.y + v.z * wv.z + v.w * wv.w;
        }
    }
    float pprev = 0.0f;
    if (wrp == 0 && start > 0) {
        const float4 a = ((const float4*)(enc + ((size_t)b * WTOT + start - 1) * HDIM))[lane];
        pprev = a.x * wv.x + a.y * wv.y + a.z * wv.z + a.w * wv.w;
    }
    __syncthreads();
    const float bias = bias_sh;
    #pragma unroll
    for (int i = 0; i < 8; i++) {
        float s = warp_sum(pr[i]);
        if (lane == 0) s_sh[wrp + 8 * i] = s + bias;
    }
    if (wrp == 0 && start > 0) {
        float s = warp_sum(pprev);
        if (lane == 0) sprev_sh = s + bias;
    }
    __syncthreads();

    if (tid < CHUNK) {
        float logit;
        if (tid == 0) logit = (start == 0) ? 0.0f : sprev_sh;
        else          logit = s_sh[tid - 1];
        e_sh[tid] = expf(logit);
    }
    __syncthreads();

    {
        const int h   = tid & 127;
        const int grp = tid >> 7;
        float acc = 0.0f;
        #pragma unroll
        for (int r = 0; r < 32; r++) {
            const int j = grp * 32 + r;
            acc += e_sh[j] * tile[j * HDIM + h];
        }
        if (grp == 0) vec_sh[h] = acc;
        __syncthreads();
        if (grp == 1) vec_sh[h] += acc;
        __syncthreads();
        if (tid < HDIM)
            g_pvec[((size_t)b * NCHUNK + chunk) * HDIM + tid] = vec_sh[tid];
    }
    if (wrp == 0) {
        float s = e_sh[lane] + e_sh[lane + 32];
        s = warp_sum(s);
        if (lane == 0) g_psum[b * NCHUNK + chunk] = s;
    }
}

// ---------------------------------------------------------------------------
// Kernel 2: decode. Gate dots are K=128 only (hh-half precomputed).
// ---------------------------------------------------------------------------
__global__ void __launch_bounds__(1024) decode_kernel(
    const float* __restrict__ input,
    const float* __restrict__ h0,
    const float* __restrict__ c0,
    const float* __restrict__ inp_W, const float* __restrict__ inp_b,
    const float* __restrict__ W_ih0,
    const float* __restrict__ W_ih1,
    float* __restrict__ out)
{
    __shared__ float cat_sh[256];
    __shared__ float xin_sh[HDIM];
    __shared__ float gate_sh[512];
    __shared__ float h1_sh[HDIM];
    __shared__ float c0_sh[2 * HDIM];
    __shared__ float vred[8][HDIM];
    __shared__ float sarr[NCHUNK];
    __shared__ float S_sh;

    const int b = blockIdx.x;
    const int tid = threadIdx.x, lane = tid & 31, wrp = tid >> 5;

    // Prefetch c0 (both layers) early so pointwise stages never stall on DRAM.
    if (tid < HDIM) {
        c0_sh[tid]        = c0[b * HDIM + tid];
        c0_sh[HDIM + tid] = c0[BATCH * HDIM + b * HDIM + tid];
    }

    // Stage 0: reduce attention partials
    if (tid < NCHUNK) sarr[tid] = g_psum[b * NCHUNK + tid];
    {
        const int h = tid & 127, grp = tid >> 7;
        float v = 0.0f;
        #pragma unroll
        for (int c = 0; c < 8; c++)
            v += g_pvec[((size_t)b * NCHUNK + grp * 8 + c) * HDIM + h];
        vred[grp][h] = v;
    }
    __syncthreads();
    float vcol = 0.0f;
    if (tid < HDIM) {
        #pragma unroll
        for (int g = 0; g < 8; g++) vcol += vred[g][tid];
    }
    if (wrp == 0) {
        float s = sarr[lane] + sarr[lane + 32];
        s = warp_sum(s);
        if (lane == 0) S_sh = s;
    }
    __syncthreads();
    if (tid < HDIM) {
        cat_sh[tid]        = vcol / S_sh;
        cat_sh[HDIM + tid] = input[b * HDIM + tid];
    }
    __syncthreads();

    // xin: 32 warps x 4 outputs, K=256
    #pragma unroll
    for (int t = 0; t < 4; t++) {
        const int i = wrp * 4 + t;
        const float4* wrow = (const float4*)(inp_W + i * 256);
        const float4 a0 = wrow[lane];
        const float4 a1 = wrow[lane + 32];
        const float4 c0v = ((const float4*)cat_sh)[lane];
        const float4 c1v = ((const float4*)cat_sh)[lane + 32];
        float p = a0.x * c0v.x + a0.y * c0v.y + a0.z * c0v.z + a0.w * c0v.w
                + a1.x * c1v.x + a1.y * c1v.y + a1.z * c1v.z + a1.w * c1v.w;
        p = warp_sum(p);
        if (lane == 0) xin_sh[i] = p + inp_b[i];
    }
    __syncthreads();

    float* out_h1 = out + 8192 + b * HDIM;
    float* out_h2 = out + 16384 + b * HDIM;
    float* out_c1 = out + 24576 + b * HDIM;
    float* out_c2 = out + 32768 + b * HDIM;
    float* out_y  = out + b * HDIM;

    // LSTM layer 0: gate = pre0 + W_ih0 . xin  (K=128)
    {
        const float4 xv = ((const float4*)xin_sh)[lane];
        #pragma unroll 4
        for (int t = 0; t < 16; t++) {
            const int k = wrp * 16 + t;
            const float pre = g_pre0[b * 512 + k];     // issued early, overlaps shfl
            const float4 wi = ((const float4*)(W_ih0 + k * HDIM))[lane];
            float p = wi.x * xv.x + wi.y * xv.y + wi.z * xv.z + wi.w * xv.w;
            p = warp_sum(p);
            if (lane == 0) gate_sh[k] = p + pre;
        }
    }
    __syncthreads();
    if (tid < HDIM) {
        const float ig = gate_sh[tid];
        const float fg = gate_sh[128 + tid];
        const float gg = gate_sh[256 + tid];
        const float og = gate_sh[384 + tid];
        const float cn = sigmoidf_(fg) * c0_sh[tid] + sigmoidf_(ig) * tanhf(gg);
        const float hn = sigmoidf_(og) * tanhf(cn);
        h1_sh[tid]  = hn;
        out_c1[tid] = cn;
        out_h1[tid] = hn;
    }
    __syncthreads();

    // LSTM layer 1: gate = pre1 + W_ih1 . h1  (K=128)
    {
        const float4 hv = ((const float4*)h1_sh)[lane];
        #pragma unroll 4
        for (int t = 0; t < 16; t++) {
            const int k = wrp * 16 + t;
            const float pre = g_pre1[b * 512 + k];
            const float4 wi = ((const float4*)(W_ih1 + k * HDIM))[lane];
            float p = wi.x * hv.x + wi.y * hv.y + wi.z * hv.z + wi.w * hv.w;
            p = warp_sum(p);
            if (lane == 0) gate_sh[k] = p + pre;
        }
    }
    __syncthreads();
    if (tid < HDIM) {
        const float ig = gate_sh[tid];
        const float fg = gate_sh[128 + tid];
        const float gg = gate_sh[256 + tid];
        const float og = gate_sh[384 + tid];
        const float cn = sigmoidf_(fg) * c0_sh[HDIM + tid] + sigmoidf_(ig) * tanhf(gg);
        const float hn = sigmoidf_(og) * tanhf(cn);
        out_c2[tid] = cn;
        out_h2[tid] = hn;
        out_y[tid]  = hn;
    }
}

extern "C" void kernel_launch(void* const* d_in, const int* in_sizes, int n_in,
                              void* d_out, int out_size)
{
    const float* input  = (const float*)d_in[0];
    const float* h0     = (const float*)d_in[1];
    const float* c0     = (const float*)d_in[2];
    const float* enc    = (const float*)d_in[3];
    const float* attW   = (const float*)d_in[4];
    const float* attb   = (const float*)d_in[5];
    const float* inp_W  = (const float*)d_in[6];
    const float* inp_b  = (const float*)d_in[7];
    const float* W_ih0  = (const float*)d_in[8];
    const float* W_hh0  = (const float*)d_in[9];
    const float* b_ih0  = (const float*)d_in[10];
    const float* b_hh0  = (const float*)d_in[11];
    const float* W_ih1  = (const float*)d_in[12];
    const float* W_hh1  = (const float*)d_in[13];
    const float* b_ih1  = (const float*)d_in[14];
    const float* b_hh1  = (const float*)d_in[15];
    float* out = (float*)d_out;

    attn_pre_kernel<<<NPRE + NCHUNK * BATCH, 256>>>(
        enc, h0, c0, attW, attb,
        W_hh0, b_ih0, b_hh0, W_hh1, b_ih1, b_hh1);
    decode_kernel<<<BATCH, 1024>>>(input, h0, c0, inp_W, inp_b,
                                   W_ih0, W_ih1, out);
}